// round 12
// baseline (speedup 1.0000x reference)
#include <cuda_runtime.h>
#include <cstdint>

#define B_ 8
#define N_ 2048
#define F_ 64
#define O_ 64
#define ALPHA 0.2f

#define BM  64
#define BKC 16
#define KSPLIT 4
#define KPART (N_ / KSPLIT)       // 512
#define NCH (KPART / BKC)         // 32 chunks per CTA
#define SA_STRIDE 24              // perm layout: 16 slots + pad
#define SA_BUF (BM * SA_STRIDE)   // 1536 floats per buf; 2 bufs = 12288 B -> 4 CTAs/SM

// Scratch (allocation-free rule: __device__ globals)
__device__ float g_d[B_ * N_];                         // d[b,n] = rsqrt(rowsum+1)
__device__ float g_Y[(size_t)B_ * N_ * O_];            // Y = d*(X@W), fp32 row-major
__device__ float g_Yt[(size_t)B_ * (N_ / 8) * 512];    // 4 MB fragment-major tf32 Y
__device__ float g_Zp[(size_t)KSPLIT * B_ * N_ * O_];  // 16 MB K-split partials

__device__ __forceinline__ float round_tf32(float x) {
    uint32_t h;
    asm("cvt.rna.tf32.f32 %0, %1;" : "=r"(h) : "f"(x));
    return __uint_as_float(h);
}
__device__ __forceinline__ void mma8(float* c, const float* a, const float* b) {
    asm("mma.sync.aligned.m16n8k8.row.col.f32.tf32.tf32.f32 "
        "{%0,%1,%2,%3}, {%4,%5,%6,%7}, {%8,%9}, {%0,%1,%2,%3};"
        : "+f"(c[0]), "+f"(c[1]), "+f"(c[2]), "+f"(c[3])
        : "r"(__float_as_uint(a[0])), "r"(__float_as_uint(a[1])),
          "r"(__float_as_uint(a[2])), "r"(__float_as_uint(a[3])),
          "r"(__float_as_uint(b[0])), "r"(__float_as_uint(b[1])));
}

// ---------------------------------------------------------------------------
// Pass 1: rowsum -> d, Y = d*(X@W) (fp32), plus fragment-major tf32 Yt.
// One block = 8 rows = one k8 block; blockIdx.x == b*256 + k8.
// Yt layout: float idx = (b*256+k8)*512 + wn*256 + lane*8 + (j*4 + ni)
//   holding tf32(Y[8*k8 + tig + 4j][wn*32 + ni*8 + g]) with lane = g*4+tig.
// (Layout proven correct in R11.)
// ---------------------------------------------------------------------------
__global__ void __launch_bounds__(256) prep_kernel(const float* __restrict__ A,
                                                   const float* __restrict__ X,
                                                   const float* __restrict__ W) {
    __shared__ float sW[F_ * O_];
    __shared__ float sX[8][F_];
    __shared__ float sYt[576];   // skewed staging: idx = wn*288 + lane2*9 + s
    const int t = threadIdx.x;
    const int warp = t >> 5;     // row-in-block (0..7)
    const int lane = t & 31;
    const int row = blockIdx.x * 8 + warp;   // flattened [b][n]

    #pragma unroll
    for (int i = t; i < F_ * O_; i += 256) sW[i] = W[i];
    #pragma unroll
    for (int i = t; i < 8 * F_; i += 256)
        sX[i >> 6][i & 63] = X[(size_t)blockIdx.x * 8 * F_ + i];
    __syncthreads();

    const float4* arow = (const float4*)(A + (size_t)row * N_);
    float s = 0.f;
    #pragma unroll 8
    for (int i = lane; i < N_ / 4; i += 32) {
        float4 v = arow[i];
        s += (v.x + v.y) + (v.z + v.w);
    }
    #pragma unroll
    for (int off = 16; off; off >>= 1) s += __shfl_xor_sync(0xffffffffu, s, off);
    const float dd = rsqrtf(s + 1.0f);
    if (lane == 0) g_d[row] = dd;

    float acc0 = 0.f, acc1 = 0.f;
    #pragma unroll
    for (int f = 0; f < F_; f++) {
        const float xv = sX[warp][f];
        acc0 += xv * sW[f * O_ + lane];
        acc1 += xv * sW[f * O_ + lane + 32];
    }
    const float y0 = dd * acc0, y1 = dd * acc1;
    g_Y[(size_t)row * O_ + lane]      = y0;
    g_Y[(size_t)row * O_ + lane + 32] = y1;

    // Stage rounded values into skewed SMEM (conflict-free)
    const int tig = warp & 3, j = warp >> 2;
    {
        const int c0 = lane;            // wn=0
        const int lane2a = (c0 & 7) * 4 + tig;
        sYt[(lane2a * 9) + (j * 4 + ((c0 >> 3) & 3))] = round_tf32(y0);
        const int c1 = lane + 32;       // wn=1
        const int lane2b = (c1 & 7) * 4 + tig;
        sYt[288 + (lane2b * 9) + (j * 4 + ((c1 >> 3) & 3))] = round_tf32(y1);
    }
    __syncthreads();

    // Copy 512 staged floats to contiguous global block (2 per thread)
    {
        const int d0 = 2 * t;
        const int wn = d0 >> 8, lane2 = (d0 >> 3) & 31, sidx = d0 & 7;
        const int src = wn * 288 + lane2 * 9 + sidx;
        *(float2*)(g_Yt + (size_t)blockIdx.x * 512 + d0) =
            make_float2(sYt[src], sYt[src + 1]);
    }
}

// ---------------------------------------------------------------------------
// Pass 2: Z-partial = A[:, kpart] @ Y[kpart, :] single-product tf32 mma.
// BM=64, 8 warps (4 wm x 2 wn), warp tile 16x32. A via perm SMEM (LDS.64
// frags, double-buffered); Y b-frags read directly from L2-resident g_Yt,
// k8-granular 2-buffer register ping-pong. Fused A copy-out.
// grid (32,8,4) = 1024 CTAs, 4 CTAs/SM, occ ~50%.
// ---------------------------------------------------------------------------
__global__ void __launch_bounds__(256, 4) gemm_tc(const float* __restrict__ A,
                                                  float* __restrict__ outA) {
    __shared__ float sAh[2 * SA_BUF];

    const int b = blockIdx.y;
    const int ks = blockIdx.z;
    const int rowBase = blockIdx.x * BM;
    const int kBase = ks * KPART;
    const float* Ab = A + (size_t)b * N_ * N_;
    float* outAb = outA ? outA + (size_t)b * N_ * N_ : nullptr;

    const int t = threadIdx.x;
    const int w = t >> 5;
    const int lane = t & 31;
    const int g = lane >> 2;
    const int tig = lane & 3;
    const int wm = w & 3;         // 16-row block
    const int wn = w >> 2;        // 32-col block

    // A loader: thread t loads 1 float4 at row a_r, col a_c
    const int a_r = t >> 2;                  // 0..63
    const int a_c = (t & 3) * 4;
    const int a_p0 = ((a_c >> 3) << 3) + ((a_c >> 2) & 1);

    // Y fragment source: k8 blocks ks*64 .. ks*64+63; 8 floats/thread/k8
    const float* ybase = g_Yt + ((size_t)(b * 256 + ks * (KPART / 8)) * 512)
                         + wn * 256 + lane * 8;

    float4 cA, nA;
    float yA[8], yB[8];

    auto ldgA = [&](int i, float4& va) {
        va = *(const float4*)(Ab + (size_t)(rowBase + a_r) * N_ + kBase + i * BKC + a_c);
    };
    auto ldgY8 = [&](int j, float (&y)[8]) {
        const float* p = ybase + (size_t)j * 512;
        *(float4*)(y)     = *(const float4*)(p);
        *(float4*)(y + 4) = *(const float4*)(p + 4);
    };
    auto stsA = [&](int buf, const float4& va) {
        float* ph = sAh + buf * SA_BUF + a_r * SA_STRIDE + a_p0;
        ph[0] = round_tf32(va.x);
        ph[2] = round_tf32(va.y);
        ph[4] = round_tf32(va.z);
        ph[6] = round_tf32(va.w);
    };
    auto stgA = [&](int i, const float4& va) {
        if (outAb)
            *(float4*)(outAb + (size_t)(rowBase + a_r) * N_ + kBase + i * BKC + a_c) = va;
    };

    float acc[4][4];
    #pragma unroll
    for (int ni = 0; ni < 4; ni++)
        #pragma unroll
        for (int j = 0; j < 4; j++) acc[ni][j] = 0.f;

    ldgA(0, cA);
    ldgY8(0, yA);
    ldgY8(1, yB);
    stsA(0, cA);
    stgA(0, cA);
    __syncthreads();

    const int a_base = (wm * 16 + g) * SA_STRIDE + 2 * tig;

    for (int i = 0; i < NCH; i++) {
        const int buf = i & 1;
        if (i + 1 < NCH) ldgA(i + 1, nA);

        const float* ah = sAh + buf * SA_BUF + a_base;
        // k8 block 2i (kk=0): consume yA, then refill for k8 2i+2
        {
            const float2 h0 = *(const float2*)(ah);
            const float2 h1 = *(const float2*)(ah + 8 * SA_STRIDE);
            const float fah[4] = {h0.x, h1.x, h0.y, h1.y};
            #pragma unroll
            for (int ni = 0; ni < 4; ni++) {
                const float fb[2] = {yA[ni], yA[4 + ni]};
                mma8(acc[ni], fah, fb);
            }
        }
        if (i + 1 < NCH) ldgY8(2 * i + 2, yA);
        // k8 block 2i+1 (kk=1): consume yB, then refill for k8 2i+3
        {
            const float2 h0 = *(const float2*)(ah + 8);
            const float2 h1 = *(const float2*)(ah + 8 * SA_STRIDE + 8);
            const float fah[4] = {h0.x, h1.x, h0.y, h1.y};
            #pragma unroll
            for (int ni = 0; ni < 4; ni++) {
                const float fb[2] = {yB[ni], yB[4 + ni]};
                mma8(acc[ni], fah, fb);
            }
        }
        if (i + 1 < NCH) {
            ldgY8(2 * i + 3, yB);
            stsA(buf ^ 1, nA);
            stgA(i + 1, nA);
        }
        __syncthreads();
    }

    // ---- store raw partial Z to scratch ----
    float* zp = g_Zp + ((size_t)(ks * B_ + b) * N_) * O_;
    const int r0 = rowBase + wm * 16 + g;
    #pragma unroll
    for (int ni = 0; ni < 4; ni++) {
        const int col = wn * 32 + ni * 8 + 2 * tig;
        *(float2*)(zp + (size_t)r0 * O_ + col)       = make_float2(acc[ni][0], acc[ni][1]);
        *(float2*)(zp + (size_t)(r0 + 8) * O_ + col) = make_float2(acc[ni][2], acc[ni][3]);
    }
}

// ---------------------------------------------------------------------------
// Pass 3: combine 4 partials + diagonal + scale + bias + leaky.
// ---------------------------------------------------------------------------
__global__ void __launch_bounds__(256) combine_kernel(const float* __restrict__ bias,
                                                      float* __restrict__ outX) {
    const int t = threadIdx.x;
    const int r = blockIdx.x * 16 + (t >> 4);
    const int c = (t & 15) * 4;
    const size_t off = (size_t)r * O_ + c;
    const size_t part = (size_t)B_ * N_ * O_;
    const float4 z0 = *(const float4*)(g_Zp + off);
    const float4 z1 = *(const float4*)(g_Zp + part + off);
    const float4 z2 = *(const float4*)(g_Zp + 2 * part + off);
    const float4 z3 = *(const float4*)(g_Zp + 3 * part + off);
    const float4 yv = *(const float4*)(g_Y + off);
    const float4 bb = *(const float4*)(bias + c);
    const float dd = g_d[r];
    float4 o;
    o.x = dd * (((z0.x + z1.x) + (z2.x + z3.x)) + yv.x) + bb.x;
    o.y = dd * (((z0.y + z1.y) + (z2.y + z3.y)) + yv.y) + bb.y;
    o.z = dd * (((z0.z + z1.z) + (z2.z + z3.z)) + yv.z) + bb.z;
    o.w = dd * (((z0.w + z1.w) + (z2.w + z3.w)) + yv.w) + bb.w;
    o.x = fmaxf(o.x, ALPHA * o.x);
    o.y = fmaxf(o.y, ALPHA * o.y);
    o.z = fmaxf(o.z, ALPHA * o.z);
    o.w = fmaxf(o.w, ALPHA * o.w);
    *(float4*)(outX + off) = o;
}

extern "C" void kernel_launch(void* const* d_in, const int* in_sizes, int n_in,
                              void* d_out, int out_size) {
    const float* X    = (const float*)d_in[0];  // [B, N, F]
    const float* A    = (const float*)d_in[1];  // [B, N, N]
    const float* W    = (const float*)d_in[2];  // [F, O]
    const float* bias = (const float*)d_in[3];  // [O]

    const size_t nX = (size_t)B_ * N_ * O_;
    const size_t nA = (size_t)B_ * N_ * N_;
    float* outX = (float*)d_out;
    float* outA = ((size_t)out_size >= nX + nA) ? outX + nX : nullptr;

    prep_kernel<<<B_ * N_ / 8, 256>>>(A, X, W);
    dim3 grid(N_ / BM, B_, KSPLIT);
    gemm_tc<<<grid, 256>>>(A, outA);
    combine_kernel<<<B_ * N_ / 16, 256>>>(bias, outX);
}

// round 14
// speedup vs baseline: 1.2161x; 1.2161x over previous
#include <cuda_runtime.h>
#include <cstdint>

#define B_ 8
#define N_ 2048
#define F_ 64
#define O_ 64
#define ALPHA 0.2f

#define BM  64
#define BKC 16
#define KSPLIT 4
#define KPART (N_ / KSPLIT)       // 512
#define NCH (KPART / BKC)         // 32 chunks per CTA
#define SA_STRIDE 24              // perm layout: 16 slots + pad
#define SA_BUF (BM * SA_STRIDE)   // 1536 floats per buf
#define SY_BUF 1024               // fragment-major Y chunk: 2 k8 x 512 floats
// static smem: 2*1536 + 2*1024 = 5120 floats = 20480 B -> 4 CTAs/SM

// Scratch (allocation-free rule: __device__ globals)
__device__ float g_d[B_ * N_];                         // d[b,n] = rsqrt(rowsum+1)
__device__ float g_Y[(size_t)B_ * N_ * O_];            // Y = d*(X@W), fp32 row-major
__device__ float g_Yt[(size_t)B_ * (N_ / 8) * 512];    // 4 MB fragment-major tf32 Y
__device__ float g_Zp[(size_t)KSPLIT * B_ * N_ * O_];  // 16 MB K-split partials

__device__ __forceinline__ float round_tf32(float x) {
    uint32_t h;
    asm("cvt.rna.tf32.f32 %0, %1;" : "=r"(h) : "f"(x));
    return __uint_as_float(h);
}
__device__ __forceinline__ void mma8(float* c, const float* a, const float* b) {
    asm("mma.sync.aligned.m16n8k8.row.col.f32.tf32.tf32.f32 "
        "{%0,%1,%2,%3}, {%4,%5,%6,%7}, {%8,%9}, {%0,%1,%2,%3};"
        : "+f"(c[0]), "+f"(c[1]), "+f"(c[2]), "+f"(c[3])
        : "r"(__float_as_uint(a[0])), "r"(__float_as_uint(a[1])),
          "r"(__float_as_uint(a[2])), "r"(__float_as_uint(a[3])),
          "r"(__float_as_uint(b[0])), "r"(__float_as_uint(b[1])));
}

// ---------------------------------------------------------------------------
// Pass 1: rowsum -> d, Y = d*(X@W) (fp32), plus fragment-major tf32 Yt.
// One block = 8 rows = one k8 block; blockIdx.x == b*256 + k8.
// Yt layout (pair-adjacent, pre-swizzled):
//   idx = k8blk*512 + wn*256 + L*8 + s,  L = g*4 + tig,
//   s = (ni ^ (g & 3)) * 2 + j,
//   value = tf32(Y[8*k8 + tig + 4*j][wn*32 + ni*8 + g]).
// Consumer b-frag (ni) = LDS.64 at fl2 offset L*4 + (ni ^ (g&3)).
// ---------------------------------------------------------------------------
__global__ void __launch_bounds__(256) prep_kernel(const float* __restrict__ A,
                                                   const float* __restrict__ X,
                                                   const float* __restrict__ W) {
    __shared__ float sW[F_ * O_];
    __shared__ float sX[8][F_];
    __shared__ float sYt[576];   // skewed staging: idx = wn*288 + L*9 + s
    const int t = threadIdx.x;
    const int warp = t >> 5;     // row-in-block (0..7): tig=warp&3, j=warp>>2
    const int lane = t & 31;
    const int row = blockIdx.x * 8 + warp;   // flattened [b][n]

    #pragma unroll
    for (int i = t; i < F_ * O_; i += 256) sW[i] = W[i];
    #pragma unroll
    for (int i = t; i < 8 * F_; i += 256)
        sX[i >> 6][i & 63] = X[(size_t)blockIdx.x * 8 * F_ + i];
    __syncthreads();

    const float4* arow = (const float4*)(A + (size_t)row * N_);
    float s = 0.f;
    #pragma unroll 8
    for (int i = lane; i < N_ / 4; i += 32) {
        float4 v = arow[i];
        s += (v.x + v.y) + (v.z + v.w);
    }
    #pragma unroll
    for (int off = 16; off; off >>= 1) s += __shfl_xor_sync(0xffffffffu, s, off);
    const float dd = rsqrtf(s + 1.0f);
    if (lane == 0) g_d[row] = dd;

    float acc0 = 0.f, acc1 = 0.f;
    #pragma unroll
    for (int f = 0; f < F_; f++) {
        const float xv = sX[warp][f];
        acc0 += xv * sW[f * O_ + lane];
        acc1 += xv * sW[f * O_ + lane + 32];
    }
    const float y0 = dd * acc0, y1 = dd * acc1;
    g_Y[(size_t)row * O_ + lane]      = y0;
    g_Y[(size_t)row * O_ + lane + 32] = y1;

    // Stage rounded values into skewed staging smem.
    // For col c (within wn half): g = c&7, ni = (c>>3)&3, L = (c&7)*4 + tig,
    // s = (ni ^ (c&3))*2 + j.
    const int tig = warp & 3, j = warp >> 2;
    {
        const int c0 = lane;            // wn=0
        const int L0 = (c0 & 7) * 4 + tig;
        const int s0 = ((((c0 >> 3) & 3) ^ (c0 & 3)) << 1) + j;
        sYt[L0 * 9 + s0] = round_tf32(y0);
        const int c1 = lane;            // wn=1 half, same local col math
        const int L1 = (c1 & 7) * 4 + tig;
        const int s1 = ((((c1 >> 3) & 3) ^ (c1 & 3)) << 1) + j;
        sYt[288 + L1 * 9 + s1] = round_tf32(y1);
    }
    __syncthreads();

    // Copy 512 staged floats to contiguous global block (2 per thread)
    {
        const int d0 = 2 * t;
        const int wn = d0 >> 8, L = (d0 >> 3) & 31, sidx = d0 & 7;
        const int src = wn * 288 + L * 9 + sidx;
        *(float2*)(g_Yt + (size_t)blockIdx.x * 512 + d0) =
            make_float2(sYt[src], sYt[src + 1]);
    }
}

// ---------------------------------------------------------------------------
// Pass 2: Z-partial = A[:, kpart] @ Y[kpart, :] single-product tf32 mma.
// BM=64, 8 warps (4 wm x 2 wn), warp tile 16x32. A via perm SMEM (LDS.64
// frags); Y chunk memcpy'd from pre-packed g_Yt (1 LDG.128 + 1 STS.128 per
// thread per chunk), consumed as LDS.64 b-frags. Fused A copy-out.
// grid (32,8,4) = 1024 CTAs, 4 CTAs/SM.
// ---------------------------------------------------------------------------
__global__ void __launch_bounds__(256, 4) gemm_tc(const float* __restrict__ A,
                                                  float* __restrict__ outA) {
    __shared__ float sAh[2 * SA_BUF];
    __shared__ float sYt[2 * SY_BUF];

    const int b = blockIdx.y;
    const int ks = blockIdx.z;
    const int rowBase = blockIdx.x * BM;
    const int kBase = ks * KPART;
    const float* Ab = A + (size_t)b * N_ * N_;
    float* outAb = outA ? outA + (size_t)b * N_ * N_ : nullptr;

    const int t = threadIdx.x;
    const int w = t >> 5;
    const int lane = t & 31;
    const int g = lane >> 2;
    const int tig = lane & 3;
    const int wm = w & 3;         // 16-row block
    const int wn = w >> 2;        // 32-col block

    // A loader: thread t loads 1 float4 at row a_r, col a_c
    const int a_r = t >> 2;                  // 0..63
    const int a_c = (t & 3) * 4;
    const int a_p0 = ((a_c >> 3) << 3) + ((a_c >> 2) & 1);

    // Yt source: chunk i covers k8 blocks 2i, 2i+1 (within this ks part)
    const float* ytsrc = g_Yt + ((size_t)(b * 256 + ks * (KPART / 8)) * 512) + 4 * t;

    float4 cA, nA, cYv, nYv;

    auto ldgA = [&](int i, float4& va) {
        va = *(const float4*)(Ab + (size_t)(rowBase + a_r) * N_ + kBase + i * BKC + a_c);
    };
    auto ldgYt = [&](int i, float4& vy) {
        vy = *(const float4*)(ytsrc + (size_t)i * 1024);
    };
    auto stsA = [&](int buf, const float4& va) {
        float* ph = sAh + buf * SA_BUF + a_r * SA_STRIDE + a_p0;
        ph[0] = round_tf32(va.x);
        ph[2] = round_tf32(va.y);
        ph[4] = round_tf32(va.z);
        ph[6] = round_tf32(va.w);
    };
    auto stsYt = [&](int buf, const float4& vy) {
        *(float4*)(sYt + buf * SY_BUF + 4 * t) = vy;
    };
    auto stgA = [&](int i, const float4& va) {
        if (outAb)
            *(float4*)(outAb + (size_t)(rowBase + a_r) * N_ + kBase + i * BKC + a_c) = va;
    };

    float acc[4][4];
    #pragma unroll
    for (int ni = 0; ni < 4; ni++)
        #pragma unroll
        for (int j = 0; j < 4; j++) acc[ni][j] = 0.f;

    ldgA(0, cA);
    ldgYt(0, cYv);
    stsA(0, cA);
    stsYt(0, cYv);
    stgA(0, cA);
    __syncthreads();

    const int a_base = (wm * 16 + g) * SA_STRIDE + 2 * tig;
    // Y consumer base: + kk*512 + wn*256 + lane*8 + (ni^(g&3))*2
    const int y_base = wn * 256 + lane * 8;
    const int nis[4] = {(0 ^ (g & 3)) * 2, (1 ^ (g & 3)) * 2,
                        (2 ^ (g & 3)) * 2, (3 ^ (g & 3)) * 2};

    for (int i = 0; i < NCH; i++) {
        const int buf = i & 1;
        if (i + 1 < NCH) { ldgA(i + 1, nA); ldgYt(i + 1, nYv); }

        const float* ah = sAh + buf * SA_BUF + a_base;
        const float* yh = sYt + buf * SY_BUF + y_base;
        #pragma unroll
        for (int kk = 0; kk < 2; kk++) {
            const float2 h0 = *(const float2*)(ah + kk * 8);
            const float2 h1 = *(const float2*)(ah + 8 * SA_STRIDE + kk * 8);
            const float fah[4] = {h0.x, h1.x, h0.y, h1.y};
            const float* yk = yh + kk * 512;
            #pragma unroll
            for (int ni = 0; ni < 4; ni++) {
                const float2 fbv = *(const float2*)(yk + nis[ni]);
                const float fb[2] = {fbv.x, fbv.y};
                mma8(acc[ni], fah, fb);
            }
        }

        if (i + 1 < NCH) {
            stsA(buf ^ 1, nA);
            stsYt(buf ^ 1, nYv);
            stgA(i + 1, nA);
        }
        __syncthreads();
    }

    // ---- store raw partial Z to scratch ----
    float* zp = g_Zp + ((size_t)(ks * B_ + b) * N_) * O_;
    const int r0 = rowBase + wm * 16 + g;
    #pragma unroll
    for (int ni = 0; ni < 4; ni++) {
        const int col = wn * 32 + ni * 8 + 2 * tig;
        *(float2*)(zp + (size_t)r0 * O_ + col)       = make_float2(acc[ni][0], acc[ni][1]);
        *(float2*)(zp + (size_t)(r0 + 8) * O_ + col) = make_float2(acc[ni][2], acc[ni][3]);
    }
}

// ---------------------------------------------------------------------------
// Pass 3: combine 4 partials + diagonal + scale + bias + leaky.
// ---------------------------------------------------------------------------
__global__ void __launch_bounds__(256) combine_kernel(const float* __restrict__ bias,
                                                      float* __restrict__ outX) {
    const int t = threadIdx.x;
    const int r = blockIdx.x * 16 + (t >> 4);
    const int c = (t & 15) * 4;
    const size_t off = (size_t)r * O_ + c;
    const size_t part = (size_t)B_ * N_ * O_;
    const float4 z0 = *(const float4*)(g_Zp + off);
    const float4 z1 = *(const float4*)(g_Zp + part + off);
    const float4 z2 = *(const float4*)(g_Zp + 2 * part + off);
    const float4 z3 = *(const float4*)(g_Zp + 3 * part + off);
    const float4 yv = *(const float4*)(g_Y + off);
    const float4 bb = *(const float4*)(bias + c);
    const float dd = g_d[r];
    float4 o;
    o.x = dd * (((z0.x + z1.x) + (z2.x + z3.x)) + yv.x) + bb.x;
    o.y = dd * (((z0.y + z1.y) + (z2.y + z3.y)) + yv.y) + bb.y;
    o.z = dd * (((z0.z + z1.z) + (z2.z + z3.z)) + yv.z) + bb.z;
    o.w = dd * (((z0.w + z1.w) + (z2.w + z3.w)) + yv.w) + bb.w;
    o.x = fmaxf(o.x, ALPHA * o.x);
    o.y = fmaxf(o.y, ALPHA * o.y);
    o.z = fmaxf(o.z, ALPHA * o.z);
    o.w = fmaxf(o.w, ALPHA * o.w);
    *(float4*)(outX + off) = o;
}

extern "C" void kernel_launch(void* const* d_in, const int* in_sizes, int n_in,
                              void* d_out, int out_size) {
    const float* X    = (const float*)d_in[0];  // [B, N, F]
    const float* A    = (const float*)d_in[1];  // [B, N, N]
    const float* W    = (const float*)d_in[2];  // [F, O]
    const float* bias = (const float*)d_in[3];  // [O]

    const size_t nX = (size_t)B_ * N_ * O_;
    const size_t nA = (size_t)B_ * N_ * N_;
    float* outX = (float*)d_out;
    float* outA = ((size_t)out_size >= nX + nA) ? outX + nX : nullptr;

    prep_kernel<<<B_ * N_ / 8, 256>>>(A, X, W);
    dim3 grid(N_ / BM, B_, KSPLIT);
    gemm_tc<<<grid, 256>>>(A, outA);
    combine_kernel<<<B_ * N_ / 16, 256>>>(bias, outX);
}

// round 15
// speedup vs baseline: 1.3877x; 1.1411x over previous
#include <cuda_runtime.h>
#include <cstdint>

#define B_ 8
#define N_ 2048
#define F_ 64
#define O_ 64
#define ALPHA 0.2f

#define BM  64
#define BKC 16
#define KSPLIT 4
#define KPART (N_ / KSPLIT)       // 512
#define NCH (KPART / BKC)         // 32 chunks per CTA
#define STAGES 4
#define SA_STRIDE 20              // row-major A tile pad; banks 20g+tig distinct
#define SA_TILE (BM * SA_STRIDE)  // 1280 floats
#define SY_TILE 1024              // fragment-major Y chunk: 2 k8 x 512 floats
#define STAGE_F (SA_TILE + SY_TILE)   // 2304 floats (mod 32 == 0)
// static smem: 4 * 2304 * 4 = 36864 B -> 4 CTAs/SM

// Scratch (allocation-free rule: __device__ globals)
__device__ float g_d[B_ * N_];                         // d[b,n] = rsqrt(rowsum+1)
__device__ float g_Y[(size_t)B_ * N_ * O_];            // Y = d*(X@W), fp32 row-major
__device__ float g_Yt[(size_t)B_ * (N_ / 8) * 512];    // 4 MB fragment-major tf32 Y
__device__ float g_Zp[(size_t)KSPLIT * B_ * N_ * O_];  // 16 MB K-split partials

__device__ __forceinline__ float round_tf32(float x) {
    uint32_t h;
    asm("cvt.rna.tf32.f32 %0, %1;" : "=r"(h) : "f"(x));
    return __uint_as_float(h);
}
__device__ __forceinline__ void mma8(float* c, const float* a, const float* b) {
    asm("mma.sync.aligned.m16n8k8.row.col.f32.tf32.tf32.f32 "
        "{%0,%1,%2,%3}, {%4,%5,%6,%7}, {%8,%9}, {%0,%1,%2,%3};"
        : "+f"(c[0]), "+f"(c[1]), "+f"(c[2]), "+f"(c[3])
        : "r"(__float_as_uint(a[0])), "r"(__float_as_uint(a[1])),
          "r"(__float_as_uint(a[2])), "r"(__float_as_uint(a[3])),
          "r"(__float_as_uint(b[0])), "r"(__float_as_uint(b[1])));
}
__device__ __forceinline__ void cp16(uint32_t dst, const void* src) {
    asm volatile("cp.async.cg.shared.global [%0], [%1], 16;" :: "r"(dst), "l"(src));
}

// ---------------------------------------------------------------------------
// Pass 1: rowsum -> d, Y = d*(X@W) (fp32), plus fragment-major tf32 Yt.
// (Unchanged from R14 — proven.)
// ---------------------------------------------------------------------------
__global__ void __launch_bounds__(256) prep_kernel(const float* __restrict__ A,
                                                   const float* __restrict__ X,
                                                   const float* __restrict__ W) {
    __shared__ float sW[F_ * O_];
    __shared__ float sX[8][F_];
    __shared__ float sYt[576];   // skewed staging: idx = wn*288 + L*9 + s
    const int t = threadIdx.x;
    const int warp = t >> 5;     // row-in-block (0..7): tig=warp&3, j=warp>>2
    const int lane = t & 31;
    const int row = blockIdx.x * 8 + warp;   // flattened [b][n]

    #pragma unroll
    for (int i = t; i < F_ * O_; i += 256) sW[i] = W[i];
    #pragma unroll
    for (int i = t; i < 8 * F_; i += 256)
        sX[i >> 6][i & 63] = X[(size_t)blockIdx.x * 8 * F_ + i];
    __syncthreads();

    const float4* arow = (const float4*)(A + (size_t)row * N_);
    float s = 0.f;
    #pragma unroll 8
    for (int i = lane; i < N_ / 4; i += 32) {
        float4 v = arow[i];
        s += (v.x + v.y) + (v.z + v.w);
    }
    #pragma unroll
    for (int off = 16; off; off >>= 1) s += __shfl_xor_sync(0xffffffffu, s, off);
    const float dd = rsqrtf(s + 1.0f);
    if (lane == 0) g_d[row] = dd;

    float acc0 = 0.f, acc1 = 0.f;
    #pragma unroll
    for (int f = 0; f < F_; f++) {
        const float xv = sX[warp][f];
        acc0 += xv * sW[f * O_ + lane];
        acc1 += xv * sW[f * O_ + lane + 32];
    }
    const float y0 = dd * acc0, y1 = dd * acc1;
    g_Y[(size_t)row * O_ + lane]      = y0;
    g_Y[(size_t)row * O_ + lane + 32] = y1;

    const int tig = warp & 3, j = warp >> 2;
    {
        const int c0 = lane;            // wn=0
        const int L0 = (c0 & 7) * 4 + tig;
        const int s0 = ((((c0 >> 3) & 3) ^ (c0 & 3)) << 1) + j;
        sYt[L0 * 9 + s0] = round_tf32(y0);
        const int c1 = lane;            // wn=1 half, same local col math
        const int L1 = (c1 & 7) * 4 + tig;
        const int s1 = ((((c1 >> 3) & 3) ^ (c1 & 3)) << 1) + j;
        sYt[288 + L1 * 9 + s1] = round_tf32(y1);
    }
    __syncthreads();

    {
        const int d0 = 2 * t;
        const int wn = d0 >> 8, L = (d0 >> 3) & 31, sidx = d0 & 7;
        const int src = wn * 288 + L * 9 + sidx;
        *(float2*)(g_Yt + (size_t)blockIdx.x * 512 + d0) =
            make_float2(sYt[src], sYt[src + 1]);
    }
}

// ---------------------------------------------------------------------------
// Pass 2: Z-partial = A[:, kpart] @ Y[kpart, :] single-product tf32 mma.
// cp.async 4-stage ring (3-chunk lookahead): A raw fp32 gmem->smem (HW mma
// truncates to tf32 bits), Yt pre-rounded memcpy. A copy-out via LDS.128 of
// the tile + STG. grid (32,8,4) = 1024 CTAs, 4 CTAs/SM.
// ---------------------------------------------------------------------------
__global__ void __launch_bounds__(256, 4) gemm_tc(const float* __restrict__ A,
                                                  float* __restrict__ outA) {
    __shared__ float ring[STAGES * STAGE_F];

    const int b = blockIdx.y;
    const int ks = blockIdx.z;
    const int rowBase = blockIdx.x * BM;
    const int kBase = ks * KPART;
    const float* Ab = A + (size_t)b * N_ * N_;
    float* outAb = outA ? outA + (size_t)b * N_ * N_ : nullptr;

    const int t = threadIdx.x;
    const int w = t >> 5;
    const int lane = t & 31;
    const int g = lane >> 2;
    const int tig = lane & 3;
    const int wm = w & 3;         // 16-row block
    const int wn = w >> 2;        // 32-col block

    // A loader: thread t copies 16B at row a_r, col a_c
    const int a_r = t >> 2;                  // 0..63
    const int a_c = (t & 3) * 4;
    const int a_off = a_r * SA_STRIDE + a_c; // float offset in tile (16B aligned)

    // Yt source: chunk i covers k8 blocks 2i, 2i+1 (within this ks part)
    const float* ytsrc = g_Yt + ((size_t)(b * 256 + ks * (KPART / 8)) * 512) + 4 * t;

    const uint32_t smem0 = (uint32_t)__cvta_generic_to_shared(ring);

    auto issue = [&](int stage, int i) {
        const uint32_t base = smem0 + (uint32_t)(stage * STAGE_F) * 4u;
        cp16(base + (uint32_t)a_off * 4u,
             Ab + (size_t)(rowBase + a_r) * N_ + kBase + i * BKC + a_c);
        cp16(base + (uint32_t)(SA_TILE + 4 * t) * 4u, ytsrc + (size_t)i * 1024);
    };

    float acc[4][4];
    #pragma unroll
    for (int ni = 0; ni < 4; ni++)
        #pragma unroll
        for (int j = 0; j < 4; j++) acc[ni][j] = 0.f;

    // Prologue: issue stages 0..2
    #pragma unroll
    for (int s = 0; s < 3; s++) {
        issue(s, s);
        asm volatile("cp.async.commit_group;" ::: "memory");
    }

    const int a_base = (wm * 16 + g) * SA_STRIDE + tig;
    const int y_base = wn * 256 + lane * 8;
    const int nis[4] = {(0 ^ (g & 3)) * 2, (1 ^ (g & 3)) * 2,
                        (2 ^ (g & 3)) * 2, (3 ^ (g & 3)) * 2};

    for (int i = 0; i < NCH; i++) {
        asm volatile("cp.async.wait_group 2;" ::: "memory");
        __syncthreads();
        if (i + 3 < NCH) issue((i + 3) & (STAGES - 1), i + 3);
        asm volatile("cp.async.commit_group;" ::: "memory");

        const float* sa = ring + (i & (STAGES - 1)) * STAGE_F;
        const float* sy = sa + SA_TILE;
        const float* ah = sa + a_base;
        #pragma unroll
        for (int kk = 0; kk < 2; kk++) {
            const float fah[4] = {ah[kk * 8], ah[8 * SA_STRIDE + kk * 8],
                                  ah[kk * 8 + 4], ah[8 * SA_STRIDE + kk * 8 + 4]};
            const float* yk = sy + kk * 512 + y_base;
            #pragma unroll
            for (int ni = 0; ni < 4; ni++) {
                const float2 fbv = *(const float2*)(yk + nis[ni]);
                const float fb[2] = {fbv.x, fbv.y};
                mma8(acc[ni], fah, fb);
            }
        }
        // A copy-through from the smem tile
        if (outAb) {
            const float4 v = *(const float4*)(sa + a_off);
            *(float4*)(outAb + (size_t)(rowBase + a_r) * N_ + kBase + i * BKC + a_c) = v;
        }
        __syncthreads();
    }

    // ---- store raw partial Z to scratch ----
    float* zp = g_Zp + ((size_t)(ks * B_ + b) * N_) * O_;
    const int r0 = rowBase + wm * 16 + g;
    #pragma unroll
    for (int ni = 0; ni < 4; ni++) {
        const int col = wn * 32 + ni * 8 + 2 * tig;
        *(float2*)(zp + (size_t)r0 * O_ + col)       = make_float2(acc[ni][0], acc[ni][1]);
        *(float2*)(zp + (size_t)(r0 + 8) * O_ + col) = make_float2(acc[ni][2], acc[ni][3]);
    }
}

// ---------------------------------------------------------------------------
// Pass 3: combine 4 partials + diagonal + scale + bias + leaky.
// ---------------------------------------------------------------------------
__global__ void __launch_bounds__(256) combine_kernel(const float* __restrict__ bias,
                                                      float* __restrict__ outX) {
    const int t = threadIdx.x;
    const int r = blockIdx.x * 16 + (t >> 4);
    const int c = (t & 15) * 4;
    const size_t off = (size_t)r * O_ + c;
    const size_t part = (size_t)B_ * N_ * O_;
    const float4 z0 = *(const float4*)(g_Zp + off);
    const float4 z1 = *(const float4*)(g_Zp + part + off);
    const float4 z2 = *(const float4*)(g_Zp + 2 * part + off);
    const float4 z3 = *(const float4*)(g_Zp + 3 * part + off);
    const float4 yv = *(const float4*)(g_Y + off);
    const float4 bb = *(const float4*)(bias + c);
    const float dd = g_d[r];
    float4 o;
    o.x = dd * (((z0.x + z1.x) + (z2.x + z3.x)) + yv.x) + bb.x;
    o.y = dd * (((z0.y + z1.y) + (z2.y + z3.y)) + yv.y) + bb.y;
    o.z = dd * (((z0.z + z1.z) + (z2.z + z3.z)) + yv.z) + bb.z;
    o.w = dd * (((z0.w + z1.w) + (z2.w + z3.w)) + yv.w) + bb.w;
    o.x = fmaxf(o.x, ALPHA * o.x);
    o.y = fmaxf(o.y, ALPHA * o.y);
    o.z = fmaxf(o.z, ALPHA * o.z);
    o.w = fmaxf(o.w, ALPHA * o.w);
    *(float4*)(outX + off) = o;
}

extern "C" void kernel_launch(void* const* d_in, const int* in_sizes, int n_in,
                              void* d_out, int out_size) {
    const float* X    = (const float*)d_in[0];  // [B, N, F]
    const float* A    = (const float*)d_in[1];  // [B, N, N]
    const float* W    = (const float*)d_in[2];  // [F, O]
    const float* bias = (const float*)d_in[3];  // [O]

    const size_t nX = (size_t)B_ * N_ * O_;
    const size_t nA = (size_t)B_ * N_ * N_;
    float* outX = (float*)d_out;
    float* outA = ((size_t)out_size >= nX + nA) ? outX + nX : nullptr;

    prep_kernel<<<B_ * N_ / 8, 256>>>(A, X, W);
    dim3 grid(N_ / BM, B_, KSPLIT);
    gemm_tc<<<grid, 256>>>(A, outA);
    combine_kernel<<<B_ * N_ / 16, 256>>>(bias, outX);
}

// round 16
// speedup vs baseline: 1.3987x; 1.0080x over previous
#include <cuda_runtime.h>
#include <cstdint>

#define B_ 8
#define N_ 2048
#define F_ 64
#define O_ 64
#define ALPHA 0.2f

#define BM  64
#define BKC 16
#define KSPLIT 4
#define KPART (N_ / KSPLIT)       // 512
#define NCH (KPART / BKC)         // 32 chunks per CTA
#define STAGES 4
#define SA_STRIDE 20              // row-major A tile pad; banks 20g+tig distinct
#define SA_TILE (BM * SA_STRIDE)  // 1280 floats
#define SY_TILE 1024              // fragment-major Y chunk: 2 k8 x 512 floats
#define STAGE_F (SA_TILE + SY_TILE)   // 2304 floats (mod 32 == 0)
// static smem: 4 * 2304 * 4 = 36864 B -> 4 CTAs/SM

// Scratch (allocation-free rule: __device__ globals)
__device__ float g_d[B_ * N_];                         // d[b,n] = rsqrt(rowsum+1)
__device__ float g_Y[(size_t)B_ * N_ * O_];            // Y = d*(X@W), fp32 row-major
__device__ float g_Yt[(size_t)B_ * (N_ / 8) * 512];    // 4 MB fragment-major tf32 Y
__device__ float g_Zp[(size_t)KSPLIT * B_ * N_ * O_];  // 16 MB K-split partials

__device__ __forceinline__ float round_tf32(float x) {
    uint32_t h;
    asm("cvt.rna.tf32.f32 %0, %1;" : "=r"(h) : "f"(x));
    return __uint_as_float(h);
}
__device__ __forceinline__ void mma8(float* c, const float* a, const float* b) {
    asm("mma.sync.aligned.m16n8k8.row.col.f32.tf32.tf32.f32 "
        "{%0,%1,%2,%3}, {%4,%5,%6,%7}, {%8,%9}, {%0,%1,%2,%3};"
        : "+f"(c[0]), "+f"(c[1]), "+f"(c[2]), "+f"(c[3])
        : "r"(__float_as_uint(a[0])), "r"(__float_as_uint(a[1])),
          "r"(__float_as_uint(a[2])), "r"(__float_as_uint(a[3])),
          "r"(__float_as_uint(b[0])), "r"(__float_as_uint(b[1])));
}
__device__ __forceinline__ void cp16(uint32_t dst, const void* src) {
    asm volatile("cp.async.cg.shared.global [%0], [%1], 16;" :: "r"(dst), "l"(src));
}

// ---------------------------------------------------------------------------
// Pass 1: rowsum -> d, Y = d*(X@W) (fp32), plus fragment-major tf32 Yt.
// (Unchanged — proven at 29.9us.)
// ---------------------------------------------------------------------------
__global__ void __launch_bounds__(256) prep_kernel(const float* __restrict__ A,
                                                   const float* __restrict__ X,
                                                   const float* __restrict__ W) {
    __shared__ float sW[F_ * O_];
    __shared__ float sX[8][F_];
    __shared__ float sYt[576];   // skewed staging: idx = wn*288 + L*9 + s
    const int t = threadIdx.x;
    const int warp = t >> 5;     // row-in-block (0..7): tig=warp&3, j=warp>>2
    const int lane = t & 31;
    const int row = blockIdx.x * 8 + warp;   // flattened [b][n]

    #pragma unroll
    for (int i = t; i < F_ * O_; i += 256) sW[i] = W[i];
    #pragma unroll
    for (int i = t; i < 8 * F_; i += 256)
        sX[i >> 6][i & 63] = X[(size_t)blockIdx.x * 8 * F_ + i];
    __syncthreads();

    const float4* arow = (const float4*)(A + (size_t)row * N_);
    float s = 0.f;
    #pragma unroll 8
    for (int i = lane; i < N_ / 4; i += 32) {
        float4 v = arow[i];
        s += (v.x + v.y) + (v.z + v.w);
    }
    #pragma unroll
    for (int off = 16; off; off >>= 1) s += __shfl_xor_sync(0xffffffffu, s, off);
    const float dd = rsqrtf(s + 1.0f);
    if (lane == 0) g_d[row] = dd;

    float acc0 = 0.f, acc1 = 0.f;
    #pragma unroll
    for (int f = 0; f < F_; f++) {
        const float xv = sX[warp][f];
        acc0 += xv * sW[f * O_ + lane];
        acc1 += xv * sW[f * O_ + lane + 32];
    }
    const float y0 = dd * acc0, y1 = dd * acc1;
    g_Y[(size_t)row * O_ + lane]      = y0;
    g_Y[(size_t)row * O_ + lane + 32] = y1;

    const int tig = warp & 3, j = warp >> 2;
    {
        const int c0 = lane;            // wn=0
        const int L0 = (c0 & 7) * 4 + tig;
        const int s0 = ((((c0 >> 3) & 3) ^ (c0 & 3)) << 1) + j;
        sYt[L0 * 9 + s0] = round_tf32(y0);
        const int c1 = lane;            // wn=1 half, same local col math
        const int L1 = (c1 & 7) * 4 + tig;
        const int s1 = ((((c1 >> 3) & 3) ^ (c1 & 3)) << 1) + j;
        sYt[288 + L1 * 9 + s1] = round_tf32(y1);
    }
    __syncthreads();

    {
        const int d0 = 2 * t;
        const int wn = d0 >> 8, L = (d0 >> 3) & 31, sidx = d0 & 7;
        const int src = wn * 288 + L * 9 + sidx;
        *(float2*)(g_Yt + (size_t)blockIdx.x * 512 + d0) =
            make_float2(sYt[src], sYt[src + 1]);
    }
}

// ---------------------------------------------------------------------------
// Pass 2: Z-partial = A[:, kpart] @ Y[kpart, :] single-product tf32 mma.
// cp.async 4-stage ring, 3-chunk lookahead, ONE __syncthreads per chunk:
// stage overwritten at iter i+1 is (i+4)&3 == i&3, whose readers (compute +
// copy-out of chunk i) finished before iter i+1's top barrier.
// grid (32,8,4) = 1024 CTAs, 4 CTAs/SM.
// ---------------------------------------------------------------------------
__global__ void __launch_bounds__(256, 4) gemm_tc(const float* __restrict__ A,
                                                  float* __restrict__ outA) {
    __shared__ float ring[STAGES * STAGE_F];

    const int b = blockIdx.y;
    const int ks = blockIdx.z;
    const int rowBase = blockIdx.x * BM;
    const int kBase = ks * KPART;
    const float* Ab = A + (size_t)b * N_ * N_;
    float* outAb = outA ? outA + (size_t)b * N_ * N_ : nullptr;

    const int t = threadIdx.x;
    const int w = t >> 5;
    const int lane = t & 31;
    const int g = lane >> 2;
    const int tig = lane & 3;
    const int wm = w & 3;         // 16-row block
    const int wn = w >> 2;        // 32-col block

    // A loader: thread t copies 16B at row a_r, col a_c
    const int a_r = t >> 2;                  // 0..63
    const int a_c = (t & 3) * 4;
    const int a_off = a_r * SA_STRIDE + a_c; // float offset in tile (16B aligned)

    // Yt source: chunk i covers k8 blocks 2i, 2i+1 (within this ks part)
    const float* ytsrc = g_Yt + ((size_t)(b * 256 + ks * (KPART / 8)) * 512) + 4 * t;

    const uint32_t smem0 = (uint32_t)__cvta_generic_to_shared(ring);

    auto issue = [&](int stage, int i) {
        const uint32_t base = smem0 + (uint32_t)(stage * STAGE_F) * 4u;
        cp16(base + (uint32_t)a_off * 4u,
             Ab + (size_t)(rowBase + a_r) * N_ + kBase + i * BKC + a_c);
        cp16(base + (uint32_t)(SA_TILE + 4 * t) * 4u, ytsrc + (size_t)i * 1024);
    };

    float acc[4][4];
    #pragma unroll
    for (int ni = 0; ni < 4; ni++)
        #pragma unroll
        for (int j = 0; j < 4; j++) acc[ni][j] = 0.f;

    // Prologue: issue stages 0..2
    #pragma unroll
    for (int s = 0; s < 3; s++) {
        issue(s, s);
        asm volatile("cp.async.commit_group;" ::: "memory");
    }

    const int a_base = (wm * 16 + g) * SA_STRIDE + tig;
    const int y_base = wn * 256 + lane * 8;
    const int nis[4] = {(0 ^ (g & 3)) * 2, (1 ^ (g & 3)) * 2,
                        (2 ^ (g & 3)) * 2, (3 ^ (g & 3)) * 2};

    for (int i = 0; i < NCH; i++) {
        asm volatile("cp.async.wait_group 2;" ::: "memory");
        __syncthreads();                       // single barrier per chunk
        if (i + 3 < NCH) issue((i + 3) & (STAGES - 1), i + 3);
        asm volatile("cp.async.commit_group;" ::: "memory");

        const float* sa = ring + (i & (STAGES - 1)) * STAGE_F;
        const float* sy = sa + SA_TILE;

        // A copy-through from the smem tile (issues early, overlaps MMAs)
        if (outAb) {
            const float4 v = *(const float4*)(sa + a_off);
            *(float4*)(outAb + (size_t)(rowBase + a_r) * N_ + kBase + i * BKC + a_c) = v;
        }

        const float* ah = sa + a_base;
        #pragma unroll
        for (int kk = 0; kk < 2; kk++) {
            const float fah[4] = {ah[kk * 8], ah[8 * SA_STRIDE + kk * 8],
                                  ah[kk * 8 + 4], ah[8 * SA_STRIDE + kk * 8 + 4]};
            const float* yk = sy + kk * 512 + y_base;
            #pragma unroll
            for (int ni = 0; ni < 4; ni++) {
                const float2 fbv = *(const float2*)(yk + nis[ni]);
                const float fb[2] = {fbv.x, fbv.y};
                mma8(acc[ni], fah, fb);
            }
        }
    }

    // ---- store raw partial Z to scratch ----
    float* zp = g_Zp + ((size_t)(ks * B_ + b) * N_) * O_;
    const int r0 = rowBase + wm * 16 + g;
    #pragma unroll
    for (int ni = 0; ni < 4; ni++) {
        const int col = wn * 32 + ni * 8 + 2 * tig;
        *(float2*)(zp + (size_t)r0 * O_ + col)       = make_float2(acc[ni][0], acc[ni][1]);
        *(float2*)(zp + (size_t)(r0 + 8) * O_ + col) = make_float2(acc[ni][2], acc[ni][3]);
    }
}

// ---------------------------------------------------------------------------
// Pass 3: combine 4 partials + diagonal + scale + bias + leaky.
// ---------------------------------------------------------------------------
__global__ void __launch_bounds__(256) combine_kernel(const float* __restrict__ bias,
                                                      float* __restrict__ outX) {
    const int t = threadIdx.x;
    const int r = blockIdx.x * 16 + (t >> 4);
    const int c = (t & 15) * 4;
    const size_t off = (size_t)r * O_ + c;
    const size_t part = (size_t)B_ * N_ * O_;
    const float4 z0 = *(const float4*)(g_Zp + off);
    const float4 z1 = *(const float4*)(g_Zp + part + off);
    const float4 z2 = *(const float4*)(g_Zp + 2 * part + off);
    const float4 z3 = *(const float4*)(g_Zp + 3 * part + off);
    const float4 yv = *(const float4*)(g_Y + off);
    const float4 bb = *(const float4*)(bias + c);
    const float dd = g_d[r];
    float4 o;
    o.x = dd * (((z0.x + z1.x) + (z2.x + z3.x)) + yv.x) + bb.x;
    o.y = dd * (((z0.y + z1.y) + (z2.y + z3.y)) + yv.y) + bb.y;
    o.z = dd * (((z0.z + z1.z) + (z2.z + z3.z)) + yv.z) + bb.z;
    o.w = dd * (((z0.w + z1.w) + (z2.w + z3.w)) + yv.w) + bb.w;
    o.x = fmaxf(o.x, ALPHA * o.x);
    o.y = fmaxf(o.y, ALPHA * o.y);
    o.z = fmaxf(o.z, ALPHA * o.z);
    o.w = fmaxf(o.w, ALPHA * o.w);
    *(float4*)(outX + off) = o;
}

extern "C" void kernel_launch(void* const* d_in, const int* in_sizes, int n_in,
                              void* d_out, int out_size) {
    const float* X    = (const float*)d_in[0];  // [B, N, F]
    const float* A    = (const float*)d_in[1];  // [B, N, N]
    const float* W    = (const float*)d_in[2];  // [F, O]
    const float* bias = (const float*)d_in[3];  // [O]

    const size_t nX = (size_t)B_ * N_ * O_;
    const size_t nA = (size_t)B_ * N_ * N_;
    float* outX = (float*)d_out;
    float* outA = ((size_t)out_size >= nX + nA) ? outX + nX : nullptr;

    prep_kernel<<<B_ * N_ / 8, 256>>>(A, X, W);
    dim3 grid(N_ / BM, B_, KSPLIT);
    gemm_tc<<<grid, 256>>>(A, outA);
    combine_kernel<<<B_ * N_ / 16, 256>>>(bias, outX);
}